// round 15
// baseline (speedup 1.0000x reference)
#include <cuda_runtime.h>
#include <cstdint>

// Problem constants
#define NN 16      // N (both u and v)
#define CC 4       // C
#define HH 32
#define WW 32
#define SS 1024    // H*W
#define K2 9       // 3x3
#define EE 144     // C*C*K2 floats per (u,v,s) chunk
#define ST 16      // s-values per block = half an image row
#define NLANES 36  // EE/4 quads
#define NSGRP 8    // s-groups (each handles 2 s)
#define NTHREADS (NSGRP * NLANES)  // 288

// x smem tile: [u(16)][c(4)][row(3)][col(20: j=0..17 used = gcols w0-1..w0+16)]
#define XS_FLOATS (NN * CC * 3 * 20)   // 3840 floats = 15360 B
#define XS_USTRIDE (CC * 3 * 20)       // 240 floats per u-slab

__global__ __launch_bounds__(NTHREADS)
void plastic_edges_kernel(const float* __restrict__ x,
                          const float* __restrict__ weight,
                          const float* __restrict__ chan_map,
                          const float* __restrict__ mask,
                          float* __restrict__ out) {
    __shared__ __align__(16) float xs[XS_FLOATS];   // [u][c][3][20]; reused as red[]
    __shared__ float cm_sh[NN * 16];                // [u][c*4+o]

    const int t    = threadIdx.x;
    const int bx   = blockIdx.x;           // 0..63
    const int h    = bx >> 1;
    const int w0   = (bx & 1) << 4;
    const int bs0  = h * 32 + w0;          // s tile base
    const int v    = blockIdx.y;           // one v per block
    const int sgrp = t / NLANES;           // 0..7
    const int lane = t % NLANES;           // 0..35 (quad index)

    // ---- stage cm_sh[u][c*4+o] = chan_map[u,v,c,o] * mask[u,v] ----
    if (t < 256) {
        int u  = t >> 4;
        int co = t & 15;
        int uv = u * NN + v;
        cm_sh[t] = chan_map[uv * 16 + co] * mask[uv];
    }
    // ---- stage raw x rows into xs ----
    for (int i = t; i < XS_FLOATS; i += NTHREADS) xs[i] = 0.0f;
    __syncthreads();
    for (int i = t; i < NN * CC * 3 * 18; i += NTHREADS) {
        int j  = i % 18;                   // local col 0..17 -> gcol w0-1+j
        int rr = (i / 18) % 3;             // rows h-1..h+1
        int uc = i / 54;                   // u*4 + c
        int r  = h + rr - 1;
        int gc = w0 - 1 + j;
        if ((unsigned)r < 32u && (unsigned)gc < 32u)
            xs[(uc * 3 + rr) * 20 + j] = x[(uc * 32 + r) * 32 + gc];
    }

    // per-thread static decode for quad p = lane*4 + e
    // x value for (p, s0+i): xs[u][c][ki][ (sgrp*2+i) + kj ]
    int cmi[4];   // cm index c*4+o
    int xofe[4];  // float index within a u-slab (includes sl0)
    {
        int p0 = lane * 4;
        int c  = p0 / 36;                  // constant across the quad
#pragma unroll
        for (int e = 0; e < 4; e++) {
            int p  = p0 + e;
            int o  = (p % 36) / 9;
            int k  = p % 9;
            int ki = k / 3, kj = k % 3;
            cmi[e]  = c * 4 + o;
            xofe[e] = (c * 3 + ki) * 20 + kj + sgrp * 2;
        }
    }

    // weight pointers for this thread's two s-rows
    const size_t ustride = (size_t)NN * SS * EE;   // elements between u slabs
    const float* wp0 = weight + ((size_t)v * SS + bs0 + sgrp * 2) * EE + lane * 4;
    const float* wp1 = wp0 + EE;

    __syncthreads();   // xs fully staged

    // ---- register-pipelined main loop: prefetch distance 2, 3 slots ----
    float4 wr0[3], wr1[3];
    wr0[0] = __ldcs((const float4*)(wp0));
    wr1[0] = __ldcs((const float4*)(wp1));
    wr0[1] = __ldcs((const float4*)(wp0 + ustride));
    wr1[1] = __ldcs((const float4*)(wp1 + ustride));

    float acc0[4], acc1[4];
#pragma unroll
    for (int e = 0; e < 4; e++) { acc0[e] = 0.0f; acc1[e] = 0.0f; }

#pragma unroll
    for (int u = 0; u < NN; u++) {
        // prefetch u+2 into the slot freed at step u-1
        if (u + 2 < NN) {
            const float* b = wp0 + (size_t)(u + 2) * ustride;
            wr0[(u + 2) % 3] = __ldcs((const float4*)(b));
            wr1[(u + 2) % 3] = __ldcs((const float4*)(b + EE));
        }
        // operand prep from smem (weight-independent)
        const float* xu = xs + u * XS_USTRIDE;
        float xc0[4], xc1[4];
#pragma unroll
        for (int e = 0; e < 4; e++) {
            float cmv = cm_sh[u * 16 + cmi[e]];
            xc0[e] = xu[xofe[e]] * cmv;
            xc1[e] = xu[xofe[e] + 1] * cmv;
        }
        // consume registers loaded 2 steps ago
        float4 wA = wr0[u % 3];
        float4 wB = wr1[u % 3];
        acc0[0] = fmaf(wA.x, xc0[0], acc0[0]);
        acc0[1] = fmaf(wA.y, xc0[1], acc0[1]);
        acc0[2] = fmaf(wA.z, xc0[2], acc0[2]);
        acc0[3] = fmaf(wA.w, xc0[3], acc0[3]);
        acc1[0] = fmaf(wB.x, xc1[0], acc1[0]);
        acc1[1] = fmaf(wB.y, xc1[1], acc1[1]);
        acc1[2] = fmaf(wB.z, xc1[2], acc1[2]);
        acc1[3] = fmaf(wB.w, xc1[3], acc1[3]);
    }

    // ---- c-reduction via shared (reuse xs), fused fold scatter ----
    __syncthreads();   // all xs reads done; safe to overwrite
    float* red = xs;   // [16 s][144] = 9216 B <= 15360 B
    {
        float4 pk0 = make_float4(acc0[0], acc0[1], acc0[2], acc0[3]);
        float4 pk1 = make_float4(acc1[0], acc1[1], acc1[2], acc1[3]);
        *(float4*)&red[(sgrp * 2 + 0) * EE + lane * 4] = pk0;
        *(float4*)&red[(sgrp * 2 + 1) * EE + lane * 4] = pk1;
    }
    __syncthreads();

    // 16*36 = 576 (s, o*9+k) outputs; sum 4 c-slices each; fold-scatter
    for (int r = t; r < ST * 36; r += NTHREADS) {
        int sl = r / 36;
        int ok = r % 36;             // o*9 + k
        int o  = ok / 9, k = ok % 9;
        const float* rb = &red[sl * EE + ok];
        float val = rb[0] + rb[36] + rb[72] + rb[108];
        // fold: channel index ch = k*C + o decoded as (cf, fi, fj)
        int ch  = k * CC + o;
        int cf  = ch / 9;
        int rem = ch % 9;
        int fi  = rem / 3, fj = rem % 3;
        int s = bs0 + sl;
        int hh = s >> 5, w = s & 31;
        int y = hh + fi - 1, xx = w + fj - 1;
        if ((unsigned)y < 32u && (unsigned)xx < 32u)
            atomicAdd(&out[((v * CC + cf) * HH + y) * WW + xx], val);
    }
}

extern "C" void kernel_launch(void* const* d_in, const int* in_sizes, int n_in,
                              void* d_out, int out_size) {
    // identify inputs by element count (robust to ordering)
    const float *x = nullptr, *wt = nullptr, *cm = nullptr, *mk = nullptr;
    for (int i = 0; i < n_in; i++) {
        switch (in_sizes[i]) {
            case NN * CC * HH * WW:           x  = (const float*)d_in[i]; break; // 65536
            case NN * NN * SS * CC * CC * K2: wt = (const float*)d_in[i]; break; // 37748736
            case NN * NN * CC * CC:           cm = (const float*)d_in[i]; break; // 4096
            case NN * NN:                     mk = (const float*)d_in[i]; break; // 256
            default: break;
        }
    }
    float* out = (float*)d_out;

    cudaMemsetAsync(out, 0, (size_t)out_size * sizeof(float), 0);

    dim3 grid(SS / ST, NN);                  // (64, 16) = 1024 blocks
    plastic_edges_kernel<<<grid, NTHREADS, 0, 0>>>(x, wt, cm, mk, out);
}